// round 11
// baseline (speedup 1.0000x reference)
#include <cuda_runtime.h>
#include <math.h>

#define Nn   8000
#define NPc  1000
#define Bc   8
#define Fc   1000
#define HCc  32
#define TRIc 499500
#define HIDc 128
#define EPSc 1e-5f
#define HPLANE (Bc * NPc * HCc)

typedef unsigned long long u64;

// ---------------- persistent scratch ----------------
__device__ int    g_bar[32];
__device__ int    g_cursor;                 // gemm dynamic chunk cursor (memset to 0 per launch)
__device__ float  g_hbuf[2 * HPLANE];       // h planes (layers 0,1)
__device__ float  g_emb[Bc * 96];
__device__ float  g_y1[Bc * HIDc];

// monotonic N-block barrier (replay-safe, never reset)
__device__ __forceinline__ void gbarN(int slot, int nb) {
    __syncthreads();
    if (threadIdx.x == 0) {
        __threadfence();
        int r = atomicAdd(&g_bar[slot], 1);
        int target = (r / nb + 1) * nb;
        while (atomicAdd(&g_bar[slot], 0) < target) { }
    }
    __syncthreads();
}

// ---------------- f32x2 packed helpers ----------------
__device__ __forceinline__ u64 pk2(float a, float b) {
    u64 r;
    asm("mov.b64 %0, {%1, %2};" : "=l"(r) : "r"(__float_as_uint(a)), "r"(__float_as_uint(b)));
    return r;
}
__device__ __forceinline__ u64 ffma2(u64 a, u64 b, u64 c) {
    u64 d;
    asm("fma.rn.f32x2 %0, %1, %2, %3;" : "=l"(d) : "l"(a), "l"(b), "l"(c));
    return d;
}
__device__ __forceinline__ float2 upk(u64 a) {
    unsigned lo, hi;
    asm("mov.b64 {%0, %1}, %2;" : "=r"(lo), "=r"(hi) : "l"(a));
    return make_float2(__uint_as_float(lo), __uint_as_float(hi));
}

// fast tanh: exp-based, no overflow, rel err ~1e-6
__device__ __forceinline__ float ftanh(float x) {
    float ax = fabsf(x);
    float e = __expf(-2.f * ax);
    float r = __fdividef(1.f - e, 1.f + e);
    return copysignf(r, x);
}

// ---------------- cheb smem layout (floats) ----------------
#define SM_A    0          // 8000  (float8 state per node)     | aliased: pDeg/pCnt/pCur
#define SM_B    8000       // 8000                              | aliased: pScan
#define SM_EM   16000      // 20000 (float2 meta per edge: {w, idx-bits})
#define SM_ROW  36000      // 1008
#define SM_W    37008      // 1280 (5 x 32 x 8)
#define SM_POOL 38288      // 256  (32 warps x 8)
#define SM_TOT  38544      // 154176 bytes

// ---------------- float8 smem gather (packed f32x2, unroll 2) ----------------
__device__ __forceinline__ void gat8(const float* __restrict__ S,
                                     const float2* __restrict__ sEm,
                                     const int* __restrict__ sRow,
                                     int d, float g[8]) {
    u64 a0 = 0, a1 = 0, a2 = 0, a3 = 0;
    int i0 = sRow[d], i1 = sRow[d + 1];
    int i = i0;
    for (; i + 2 <= i1; i += 2) {
        float2 m0 = sEm[i], m1 = sEm[i + 1];
        const float* p0 = S + (__float_as_int(m0.y) << 3);
        const float* p1 = S + (__float_as_int(m1.y) << 3);
        ulonglong2 s0a = *(const ulonglong2*)p0;
        ulonglong2 s0b = *(const ulonglong2*)(p0 + 4);
        ulonglong2 s1a = *(const ulonglong2*)p1;
        ulonglong2 s1b = *(const ulonglong2*)(p1 + 4);
        u64 w0 = pk2(m0.x, m0.x), w1 = pk2(m1.x, m1.x);
        a0 = ffma2(w0, s0a.x, a0); a1 = ffma2(w0, s0a.y, a1);
        a2 = ffma2(w0, s0b.x, a2); a3 = ffma2(w0, s0b.y, a3);
        a0 = ffma2(w1, s1a.x, a0); a1 = ffma2(w1, s1a.y, a1);
        a2 = ffma2(w1, s1b.x, a2); a3 = ffma2(w1, s1b.y, a3);
    }
    if (i < i1) {
        float2 m0 = sEm[i];
        const float* p0 = S + (__float_as_int(m0.y) << 3);
        ulonglong2 s0a = *(const ulonglong2*)p0;
        ulonglong2 s0b = *(const ulonglong2*)(p0 + 4);
        u64 w0 = pk2(m0.x, m0.x);
        a0 = ffma2(w0, s0a.x, a0); a1 = ffma2(w0, s0a.y, a1);
        a2 = ffma2(w0, s0b.x, a2); a3 = ffma2(w0, s0b.y, a3);
    }
    float2 f0 = upk(a0), f1 = upk(a1), f2 = upk(a2), f3 = upk(a3);
    g[0] = f0.x; g[1] = f0.y; g[2] = f1.x; g[3] = f1.y;
    g[4] = f2.x; g[5] = f2.y; g[6] = f3.x; g[7] = f3.y;
}

__device__ __forceinline__ void st8(float* S, int d, const float v[8]) {
    *(float4*)(S + d * 8)     = make_float4(v[0], v[1], v[2], v[3]);
    *(float4*)(S + d * 8 + 4) = make_float4(v[4], v[5], v[6], v[7]);
}
__device__ __forceinline__ void ld8(const float* S, int d, float v[8]) {
    float4 a = *(const float4*)(S + d * 8);
    float4 b = *(const float4*)(S + d * 8 + 4);
    v[0] = a.x; v[1] = a.y; v[2] = a.z; v[3] = a.w;
    v[4] = b.x; v[5] = b.y; v[6] = b.z; v[7] = b.w;
}

// v-term load: mode 0 -> cw0 planes (layer 0); mode 1 -> thread-private vloc
__device__ __forceinline__ void load_v(int mode, const float* __restrict__ vsrc,
                                       const float* vloc, int k, int d, int ch0, float v[8]) {
    if (mode == 0) {
        float4 a = __ldg((const float4*)(vsrc + k * 32000 + d * 32 + ch0));
        float4 b = __ldg((const float4*)(vsrc + k * 32000 + d * 32 + ch0 + 4));
        v[0] = a.x; v[1] = a.y; v[2] = a.z; v[3] = a.w;
        v[4] = b.x; v[5] = b.y; v[6] = b.z; v[7] = b.w;
    } else {
#pragma unroll
        for (int c = 0; c < 8; c++) v[c] = vloc[k * 8 + c];
    }
}

// ---------------- v-table pass: vloc[k*8+c] = h[d][:] @ W[k][:, ch0+c] ----------------
__device__ void vpass(const float* __restrict__ hsrc,    // batch base [d][32]
                      const float* __restrict__ cwL,     // (5,32,32)
                      float* vloc, float* sW, int ch0, int t)
{
    for (int idx = t; idx < 5 * 32 * 8; idx += 1024) {
        int c = idx & 7, j = (idx >> 3) & 31, k = idx >> 8;
        sW[idx] = __ldg(cwL + k * 1024 + j * 32 + ch0 + c);
    }
    __syncthreads();
    int d = t;
    if (d < NPc) {
        float4 hv[8];
#pragma unroll
        for (int q = 0; q < 8; q++)
            hv[q] = __ldcg((const float4*)(hsrc + d * 32 + q * 4));
        const float* hh = (const float*)hv;
#pragma unroll
        for (int k = 0; k < 5; k++) {
            u64 a0 = 0, a1 = 0, a2 = 0, a3 = 0;
#pragma unroll
            for (int j = 0; j < 32; j++) {
                u64 hj2 = pk2(hh[j], hh[j]);
                const ulonglong2* wr = (const ulonglong2*)&sW[k * 256 + j * 8];
                ulonglong2 w01 = wr[0], w23 = wr[1];
                a0 = ffma2(hj2, w01.x, a0); a1 = ffma2(hj2, w01.y, a1);
                a2 = ffma2(hj2, w23.x, a2); a3 = ffma2(hj2, w23.y, a3);
            }
            float2 f0 = upk(a0), f1 = upk(a1), f2 = upk(a2), f3 = upk(a3);
            vloc[k * 8 + 0] = f0.x; vloc[k * 8 + 1] = f0.y;
            vloc[k * 8 + 2] = f1.x; vloc[k * 8 + 3] = f1.y;
            vloc[k * 8 + 4] = f2.x; vloc[k * 8 + 5] = f2.y;
            vloc[k * 8 + 6] = f3.x; vloc[k * 8 + 7] = f3.y;
        }
    }
    __syncthreads();
}

// ---------------- one ChebConv layer: node-per-thread, 8 channels ----------------
__device__ void run_layer(int L, int mode, int b, int ch0, int t,
                          float* sA, float* sB,
                          const int* sRow, const float2* sEm,
                          const float* __restrict__ vsrc, const float* vloc,
                          const float* __restrict__ cbL, float* sPool)
{
    int d = t;
    bool act = (d < NPc);
    float v[8], g[8], f[8];

    if (act) { load_v(mode, vsrc, vloc, 4, d, ch0, v); st8(sA, d, v); }
    __syncthreads();
    if (act) {
        gat8(sA, sEm, sRow, d, g);
        load_v(mode, vsrc, vloc, 3, d, ch0, v);
#pragma unroll
        for (int c = 0; c < 8; c++) f[c] = fmaf(2.f, g[c], v[c]);
        st8(sB, d, f);
    }
    __syncthreads();
    if (act) {
        gat8(sB, sEm, sRow, d, g);
        load_v(mode, vsrc, vloc, 2, d, ch0, v);
        float o[8]; ld8(sA, d, o);
#pragma unroll
        for (int c = 0; c < 8; c++) f[c] = fmaf(2.f, g[c], v[c]) - o[c];
        st8(sA, d, f);
    }
    __syncthreads();
    if (act) {
        gat8(sA, sEm, sRow, d, g);
        load_v(mode, vsrc, vloc, 1, d, ch0, v);
        float o[8]; ld8(sB, d, o);
#pragma unroll
        for (int c = 0; c < 8; c++) f[c] = fmaf(2.f, g[c], v[c]) - o[c];
        st8(sB, d, f);
    }
    __syncthreads();
    // final: h = tanh(v0 + G(B) - A + bias); pool; store h
    float pool[8];
#pragma unroll
    for (int c = 0; c < 8; c++) pool[c] = 0.f;
    if (act) {
        gat8(sB, sEm, sRow, d, g);
        load_v(mode, vsrc, vloc, 0, d, ch0, v);
        float o[8]; ld8(sA, d, o);
        float4 bi0 = __ldg((const float4*)(cbL + ch0));
        float4 bi1 = __ldg((const float4*)(cbL + ch0 + 4));
        float bias[8] = {bi0.x, bi0.y, bi0.z, bi0.w, bi1.x, bi1.y, bi1.z, bi1.w};
        float h[8];
#pragma unroll
        for (int c = 0; c < 8; c++) {
            h[c] = ftanh(v[c] + g[c] - o[c] + bias[c]);
            pool[c] = h[c];
        }
        if (L < 2) {
            float* hp = g_hbuf + L * HPLANE + b * NPc * HCc + d * HCc + ch0;
            *(float4*)hp       = make_float4(h[0], h[1], h[2], h[3]);
            *(float4*)(hp + 4) = make_float4(h[4], h[5], h[6], h[7]);
        }
    }
    // pool reduce: warp shuffles, per-warp smem, then 8 threads store (block owns cols)
#pragma unroll
    for (int off = 16; off >= 1; off >>= 1)
#pragma unroll
        for (int c = 0; c < 8; c++)
            pool[c] += __shfl_down_sync(0xFFFFFFFFu, pool[c], off);
    int wid = t >> 5, lid = t & 31;
    if (lid == 0) {
        *(float4*)(sPool + wid * 8)     = make_float4(pool[0], pool[1], pool[2], pool[3]);
        *(float4*)(sPool + wid * 8 + 4) = make_float4(pool[4], pool[5], pool[6], pool[7]);
    }
    __syncthreads();
    if (t < 8) {
        float s = 0.f;
#pragma unroll
        for (int w = 0; w < 32; w++) s += sPool[w * 8 + t];
        g_emb[b * 96 + L * 32 + ch0 + t] = s;
    }
    __syncthreads();
}

// ---------------- the cheb kernel: 32 blocks x 1024 threads ----------------
__global__ void __launch_bounds__(1024, 1)
cheb_kernel(const int* __restrict__ src, const int* __restrict__ dst, int E,
            const float* __restrict__ cw0, const float* __restrict__ cb0,
            const float* __restrict__ cw1, const float* __restrict__ cb1,
            const float* __restrict__ cw2, const float* __restrict__ cb2)
{
    extern __shared__ float sm[];
    float* sA   = sm + SM_A;
    float* sB   = sm + SM_B;
    float2* sEm = (float2*)(sm + SM_EM);
    int* sRow   = (int*)(sm + SM_ROW);
    float* sW   = sm + SM_W;
    float* sPool= sm + SM_POOL;
    // CSR-build scratch aliased over sA/sB (dead until first pass)
    int* pDeg  = (int*)(sm + SM_A);
    int* pCnt  = (int*)(sm + SM_A) + 1000;
    int* pCur  = (int*)(sm + SM_A) + 2000;
    int* pScan = (int*)(sm + SM_B);

    const int t = threadIdx.x, blk = blockIdx.x;
    const int b = blk >> 2, r = blk & 3;
    const int ch0 = r * 8;
    const int EB = E / Bc;
    const int e0 = b * EB;
    float vloc[40];

    // ---- in-block CSR build for batch b ----
    if (t < NPc) { pDeg[t] = 0; pCnt[t] = 0; }
    __syncthreads();
    for (int e = e0 + t; e < e0 + EB; e += 1024) {
        atomicAdd(&pDeg[__ldg(src + e) - b * NPc], 1);
        atomicAdd(&pCnt[__ldg(dst + e) - b * NPc], 1);
    }
    __syncthreads();
    {   // exclusive scan of pCnt
        int c = (t < NPc) ? pCnt[t] : 0;
        pScan[t] = c;
        __syncthreads();
        for (int off = 1; off < 1024; off <<= 1) {
            int v = (t >= off) ? pScan[t - off] : 0;
            __syncthreads();
            pScan[t] += v;
            __syncthreads();
        }
        if (t < NPc) { sRow[t] = pScan[t] - c; pCur[t] = pScan[t] - c; }
        if (t == 0) sRow[NPc] = pScan[1023];
    }
    __syncthreads();
    for (int e = e0 + t; e < e0 + EB; e += 1024) {
        int s_ = __ldg(src + e) - b * NPc;
        int d_ = __ldg(dst + e) - b * NPc;
        int ds = pDeg[s_], dd = pDeg[d_];
        float w = (ds > 0 && dd > 0) ? -rsqrtf((float)ds) * rsqrtf((float)dd) : 0.f;
        int pos = atomicAdd(&pCur[d_], 1);
        sEm[pos] = make_float2(w, __int_as_float(s_));
    }
    __syncthreads();   // scratch dead; sA/sB reusable

    // ---- layer 0 (v from cw0 planes) ----
    run_layer(0, 0, b, ch0, t, sA, sB, sRow, sEm, cw0, nullptr, cb0, sPool);

    __threadfence();
    gbarN(b * 2 + 0, 4);
    vpass(g_hbuf + 0 * HPLANE + b * NPc * HCc, cw1, vloc, sW, ch0, t);
    run_layer(1, 1, b, ch0, t, sA, sB, sRow, sEm, nullptr, vloc, cb1, sPool);

    __threadfence();
    gbarN(b * 2 + 1, 4);
    vpass(g_hbuf + 1 * HPLANE + b * NPc * HCc, cw2, vloc, sW, ch0, t);
    run_layer(2, 1, b, ch0, t, sA, sB, sRow, sEm, nullptr, vloc, cb2, sPool);
}

// ---------------- GEMM kernel: dynamic chunks, 8-deep prefetch ----------------
#define GNB   296
#define GCH   256
#define GNCH  ((TRIc + GCH - 1) / GCH)   // 1952

__device__ __forceinline__ void triidx(int f, int& i, int& j) {
    float disc = 3996001.0f - 8.0f * (float)f;
    float sq = sqrtf(fmaxf(disc, 0.f));
    i = (int)((1999.0f - sq) * 0.5f);
    i = max(0, min(i, Fc - 2));
    while (i + 1 <= Fc - 2 && (((long long)(i + 1) * (1999 - (i + 1))) >> 1) <= (long long)f) i++;
    while (i > 0 && (((long long)i * (1999 - i)) >> 1) > (long long)f) i--;
    int Si = (int)(((long long)i * (1999 - i)) >> 1);
    j = i + 1 + (f - Si);
}

__global__ void __launch_bounds__(256, 2)
gemm_kernel(const float* __restrict__ x, const float* __restrict__ W1,
            const float* __restrict__ bng, const float* __restrict__ bnb)
{
    __shared__ float sfb[2][GCH * 8];
    __shared__ float sred[4096];
    __shared__ int sChunk;
    int t = threadIdx.x, wp = t >> 5, l = t & 31;
    float acc[Bc][4];
#pragma unroll
    for (int b = 0; b < Bc; b++)
#pragma unroll
        for (int q = 0; q < 4; q++) acc[b][q] = 0.f;

    // grab first chunk
    if (t == 0) sChunk = atomicAdd(&g_cursor, 1);
    __syncthreads();
    int c = sChunk;
    __syncthreads();
    if (c < GNCH) {
        int f = c * GCH + t;
        float res[Bc];
        if (f < TRIc) {
            int i, j; triidx(f, i, j);
            float v[Bc]; float m = 0.f;
#pragma unroll
            for (int b = 0; b < Bc; b++) { v[b] = __ldg(x + ((size_t)(b * Fc + i) * Fc + j)); m += v[b]; }
            m *= 0.125f;
            float var = 0.f;
#pragma unroll
            for (int b = 0; b < Bc; b++) { float dd = v[b] - m; var = fmaf(dd, dd, var); }
            var *= 0.125f;
            float sc = rsqrtf(var + EPSc) * __ldg(bng + f);
            float sh = __ldg(bnb + f);
#pragma unroll
            for (int b = 0; b < Bc; b++) res[b] = (v[b] - m) * sc + sh;
        } else {
#pragma unroll
            for (int b = 0; b < Bc; b++) res[b] = 0.f;
        }
        *(float4*)&sfb[0][t * 8]     = make_float4(res[0], res[1], res[2], res[3]);
        *(float4*)&sfb[0][t * 8 + 4] = make_float4(res[4], res[5], res[6], res[7]);
    }
    __syncthreads();

    int p = 0;
    while (c < GNCH) {
        // grab next chunk
        if (t == 0) sChunk = atomicAdd(&g_cursor, 1);
        __syncthreads();
        int cn = sChunk;
        __syncthreads();
        bool hasN = (cn < GNCH);
        // prefetch next chunk's x rows into registers
        float xv[Bc]; float bgv = 0.f, bbv = 0.f; bool val = false;
        if (hasN) {
            int fN = cn * GCH + t;
            val = (fN < TRIc);
            if (val) {
                int i, j; triidx(fN, i, j);
#pragma unroll
                for (int b = 0; b < Bc; b++)
                    xv[b] = __ldg(x + ((size_t)(b * Fc + i) * Fc + j));
                bgv = __ldg(bng + fN);
                bbv = __ldg(bnb + fN);
            }
        }
        // stream W1 for chunk c: 32 rows/warp, 8 LDG.128 in flight
        {
            int fbase = c * GCH;
            int r0 = wp * 32;
            const float* buf = sfb[p];
            for (int rb = 0; rb < 32; rb += 8) {
                float4 w[8];
#pragma unroll
                for (int u = 0; u < 8; u++) {
                    int f2 = min(fbase + r0 + rb + u, TRIc - 1);
                    w[u] = __ldcs((const float4*)(W1 + (size_t)f2 * HIDc + l * 4));
                }
#pragma unroll
                for (int u = 0; u < 8; u++) {
                    int fl = r0 + rb + u;
                    float4 f0 = *(const float4*)&buf[fl * 8];
                    float4 f1 = *(const float4*)&buf[fl * 8 + 4];
                    acc[0][0] = fmaf(f0.x, w[u].x, acc[0][0]); acc[0][1] = fmaf(f0.x, w[u].y, acc[0][1]);
                    acc[0][2] = fmaf(f0.x, w[u].z, acc[0][2]); acc[0][3] = fmaf(f0.x, w[u].w, acc[0][3]);
                    acc[1][0] = fmaf(f0.y, w[u].x, acc[1][0]); acc[1][1] = fmaf(f0.y, w[u].y, acc[1][1]);
                    acc[1][2] = fmaf(f0.y, w[u].z, acc[1][2]); acc[1][3] = fmaf(f0.y, w[u].w, acc[1][3]);
                    acc[2][0] = fmaf(f0.z, w[u].x, acc[2][0]); acc[2][1] = fmaf(f0.z, w[u].y, acc[2][1]);
                    acc[2][2] = fmaf(f0.z, w[u].z, acc[2][2]); acc[2][3] = fmaf(f0.z, w[u].w, acc[2][3]);
                    acc[3][0] = fmaf(f0.w, w[u].x, acc[3][0]); acc[3][1] = fmaf(f0.w, w[u].y, acc[3][1]);
                    acc[3][2] = fmaf(f0.w, w[u].z, acc[3][2]); acc[3][3] = fmaf(f0.w, w[u].w, acc[3][3]);
                    acc[4][0] = fmaf(f1.x, w[u].x, acc[4][0]); acc[4][1] = fmaf(f1.x, w[u].y, acc[4][1]);
                    acc[4][2] = fmaf(f1.x, w[u].z, acc[4][2]); acc[4][3] = fmaf(f1.x, w[u].w, acc[4][3]);
                    acc[5][0] = fmaf(f1.y, w[u].x, acc[5][0]); acc[5][1] = fmaf(f1.y, w[u].y, acc[5][1]);
                    acc[5][2] = fmaf(f1.y, w[u].z, acc[5][2]); acc[5][3] = fmaf(f1.y, w[u].w, acc[5][3]);
                    acc[6][0] = fmaf(f1.z, w[u].x, acc[6][0]); acc[6][1] = fmaf(f1.z, w[u].y, acc[6][1]);
                    acc[6][2] = fmaf(f1.z, w[u].z, acc[6][2]); acc[6][3] = fmaf(f1.z, w[u].w, acc[6][3]);
                    acc[7][0] = fmaf(f1.w, w[u].x, acc[7][0]); acc[7][1] = fmaf(f1.w, w[u].y, acc[7][1]);
                    acc[7][2] = fmaf(f1.w, w[u].z, acc[7][2]); acc[7][3] = fmaf(f1.w, w[u].w, acc[7][3]);
                }
            }
        }
        // finish fbn for next chunk into the other buffer
        if (hasN) {
            float res[Bc];
            if (val) {
                float m = 0.f;
#pragma unroll
                for (int b = 0; b < Bc; b++) m += xv[b];
                m *= 0.125f;
                float var = 0.f;
#pragma unroll
                for (int b = 0; b < Bc; b++) { float dd = xv[b] - m; var = fmaf(dd, dd, var); }
                var *= 0.125f;
                float sc = rsqrtf(var + EPSc) * bgv;
#pragma unroll
                for (int b = 0; b < Bc; b++) res[b] = (xv[b] - m) * sc + bbv;
            } else {
#pragma unroll
                for (int b = 0; b < Bc; b++) res[b] = 0.f;
            }
            *(float4*)&sfb[p ^ 1][t * 8]     = make_float4(res[0], res[1], res[2], res[3]);
            *(float4*)&sfb[p ^ 1][t * 8 + 4] = make_float4(res[4], res[5], res[6], res[7]);
        }
        __syncthreads();
        c = cn;
        p ^= 1;
    }

    // tree reduce 8 warps -> 1
    for (int half = 4; half >= 1; half >>= 1) {
        if (wp >= half && wp < 2 * half) {
            float* reg = sred + (wp - half) * 1024;
#pragma unroll
            for (int b = 0; b < Bc; b++)
                *(float4*)&reg[b * HIDc + l * 4] =
                    make_float4(acc[b][0], acc[b][1], acc[b][2], acc[b][3]);
        }
        __syncthreads();
        if (wp < half) {
            float* reg = sred + wp * 1024;
#pragma unroll
            for (int b = 0; b < Bc; b++) {
                float4 z = *(const float4*)&reg[b * HIDc + l * 4];
                acc[b][0] += z.x; acc[b][1] += z.y; acc[b][2] += z.z; acc[b][3] += z.w;
            }
        }
        __syncthreads();
    }
    if (wp == 0) {
#pragma unroll
        for (int b = 0; b < Bc; b++)
#pragma unroll
            for (int q = 0; q < 4; q++)
                atomicAdd(&g_y1[b * HIDc + l * 4 + q], acc[b][q]);
    }
}

// ---------------- head ----------------
__global__ void head_kernel(const float* __restrict__ bnhg, const float* __restrict__ bnhb,
                            const float* __restrict__ b1,
                            const float* __restrict__ g1, const float* __restrict__ be1,
                            const float* __restrict__ W2, const float* __restrict__ b2,
                            const float* __restrict__ g2, const float* __restrict__ be2,
                            const float* __restrict__ W3, const float* __restrict__ b3,
                            const float* __restrict__ g3, const float* __restrict__ be3,
                            const float* __restrict__ W4, const float* __restrict__ b4,
                            float* __restrict__ out) {
    __shared__ float a1[8 * 128];
    __shared__ float a2[8 * 64];
    __shared__ float a3[8 * 64];
    __shared__ float lg[16];
    int t = threadIdx.x;

    if (t < 96) {
        float e[Bc]; float m = 0.f;
#pragma unroll
        for (int b = 0; b < Bc; b++) { e[b] = __ldcg(&g_emb[b * 96 + t]) * (1.f / (float)NPc); m += e[b]; }
        m *= 0.125f;
        float v = 0.f;
#pragma unroll
        for (int b = 0; b < Bc; b++) { float dd = e[b] - m; v = fmaf(dd, dd, v); }
        v *= 0.125f;
        float sc = rsqrtf(v + EPSc) * __ldg(bnhg + t);
        float sh = __ldg(bnhb + t);
#pragma unroll
        for (int b = 0; b < Bc; b++) out[16 + b * 96 + t] = (e[b] - m) * sc + sh;
    }

    for (int idx = t; idx < 1024; idx += 256) a1[idx] = __ldcg(&g_y1[idx]) + __ldg(&b1[idx & 127]);
    __syncthreads();
    if (t < 128) {
        float m = 0.f;
#pragma unroll
        for (int b = 0; b < Bc; b++) m += a1[b * 128 + t];
        m *= 0.125f;
        float v = 0.f;
#pragma unroll
        for (int b = 0; b < Bc; b++) { float dd = a1[b * 128 + t] - m; v = fmaf(dd, dd, v); }
        v *= 0.125f;
        float sc = rsqrtf(v + EPSc) * __ldg(g1 + t);
        float sh = __ldg(be1 + t);
#pragma unroll
        for (int b = 0; b < Bc; b++) {
            float z = (a1[b * 128 + t] - m) * sc + sh;
            a1[b * 128 + t] = z > 0.f ? z : 0.f;
        }
    }
    __syncthreads();
    for (int idx = t; idx < 512; idx += 256) {
        int b = idx >> 6, h = idx & 63;
        float s = __ldg(b2 + h);
        for (int j = 0; j < 128; j++) s = fmaf(a1[b * 128 + j], __ldg(W2 + j * 64 + h), s);
        a2[idx] = s;
    }
    __syncthreads();
    if (t < 64) {
        float m = 0.f;
#pragma unroll
        for (int b = 0; b < Bc; b++) m += a2[b * 64 + t];
        m *= 0.125f;
        float v = 0.f;
#pragma unroll
        for (int b = 0; b < Bc; b++) { float dd = a2[b * 64 + t] - m; v = fmaf(dd, dd, v); }
        v *= 0.125f;
        float sc = rsqrtf(v + EPSc) * __ldg(g2 + t);
        float sh = __ldg(be2 + t);
#pragma unroll
        for (int b = 0; b < Bc; b++) {
            float z = (a2[b * 64 + t] - m) * sc + sh;
            a2[b * 64 + t] = z > 0.f ? z : 0.f;
        }
    }
    __syncthreads();
    for (int idx = t; idx < 512; idx += 256) {
        int b = idx >> 6, h = idx & 63;
        float s = __ldg(b3 + h);
        for (int j = 0; j < 64; j++) s = fmaf(a2[b * 64 + j], __ldg(W3 + j * 64 + h), s);
        a3[idx] = s;
    }
    __syncthreads();
    if (t < 64) {
        float m = 0.f;
#pragma unroll
        for (int b = 0; b < Bc; b++) m += a3[b * 64 + t];
        m *= 0.125f;
        float v = 0.f;
#pragma unroll
        for (int b = 0; b < Bc; b++) { float dd = a3[b * 64 + t] - m; v = fmaf(dd, dd, v); }
        v *= 0.125f;
        float sc = rsqrtf(v + EPSc) * __ldg(g3 + t);
        float sh = __ldg(be3 + t);
#pragma unroll
        for (int b = 0; b < Bc; b++) {
            float z = (a3[b * 64 + t] - m) * sc + sh;
            a3[b * 64 + t] = z > 0.f ? z : 0.f;
        }
    }
    __syncthreads();
    if (t < 16) {
        int b = t >> 1, c = t & 1;
        float s = __ldg(b4 + c);
        for (int j = 0; j < 64; j++) s = fmaf(a3[b * 64 + j], __ldg(W4 + j * 2 + c), s);
        lg[t] = s;
    }
    __syncthreads();
    if (t < 8) {
        float l0 = lg[t * 2], l1 = lg[t * 2 + 1];
        float m = fmaxf(l0, l1);
        float lse = m + logf(expf(l0 - m) + expf(l1 - m));
        out[t * 2 + 0] = l0 - lse;
        out[t * 2 + 1] = l1 - lse;
    }
}

// ---------------- host driver ----------------
extern "C" void kernel_launch(void* const* d_in, const int* in_sizes, int n_in,
                              void* d_out, int out_size) {
    const float* x    = (const float*)d_in[0];
    const int*   ei   = (const int*)d_in[1];
    int E = in_sizes[1] / 2;
    const int* src = ei;
    const int* dst = ei + E;
    const float* cw0  = (const float*)d_in[3];
    const float* cb0  = (const float*)d_in[4];
    const float* cw1  = (const float*)d_in[5];
    const float* cb1  = (const float*)d_in[6];
    const float* cw2  = (const float*)d_in[7];
    const float* cb2  = (const float*)d_in[8];
    const float* bnhg = (const float*)d_in[9];
    const float* bnhb = (const float*)d_in[10];
    const float* bng  = (const float*)d_in[11];
    const float* bnb  = (const float*)d_in[12];
    const float* w1   = (const float*)d_in[13];
    const float* b1   = (const float*)d_in[14];
    const float* g1   = (const float*)d_in[15];
    const float* be1  = (const float*)d_in[16];
    const float* W2   = (const float*)d_in[17];
    const float* b2   = (const float*)d_in[18];
    const float* g2   = (const float*)d_in[19];
    const float* be2  = (const float*)d_in[20];
    const float* W3   = (const float*)d_in[21];
    const float* b3   = (const float*)d_in[22];
    const float* g3   = (const float*)d_in[23];
    const float* be3  = (const float*)d_in[24];
    const float* W4   = (const float*)d_in[25];
    const float* b4   = (const float*)d_in[26];
    float* out = (float*)d_out;

    void* y1ptr = nullptr;
    void* curptr = nullptr;
    cudaGetSymbolAddress(&y1ptr, g_y1);
    cudaGetSymbolAddress(&curptr, g_cursor);

    cudaStream_t s2 = 0;
    cudaEvent_t evF = 0, evJ = 0;
    bool forked = (cudaStreamCreateWithFlags(&s2, cudaStreamNonBlocking) == cudaSuccess) &&
                  (cudaEventCreateWithFlags(&evF, cudaEventDisableTiming) == cudaSuccess) &&
                  (cudaEventCreateWithFlags(&evJ, cudaEventDisableTiming) == cudaSuccess);
    if (!forked) s2 = 0;

    if (forked) {
        cudaEventRecord(evF, 0);
        cudaStreamWaitEvent(s2, evF, 0);
    }

    // cheb first (32 big-smem blocks grab their SMs immediately)
    cudaFuncSetAttribute(cheb_kernel, cudaFuncAttributeMaxDynamicSharedMemorySize,
                         SM_TOT * (int)sizeof(float));
    cheb_kernel<<<32, 1024, SM_TOT * sizeof(float)>>>(src, dst, E,
                                                      cw0, cb0, cw1, cb1, cw2, cb2);

    cudaMemsetAsync(y1ptr, 0, Bc * HIDc * sizeof(float), s2);
    cudaMemsetAsync(curptr, 0, sizeof(int), s2);
    gemm_kernel<<<GNB, 256, 0, s2>>>(x, w1, bng, bnb);
    if (forked) cudaEventRecord(evJ, s2);

    if (forked) cudaStreamWaitEvent(0, evJ, 0);
    head_kernel<<<1, 256>>>(bnhg, bnhb, b1, g1, be1, W2, b2, g2, be2,
                            W3, b3, g3, be3, W4, b4, out);
}

// round 13
// speedup vs baseline: 1.6036x; 1.6036x over previous
#include <cuda_runtime.h>
#include <math.h>

#define Nn   8000
#define NPc  1000
#define Bc   8
#define Fc   1000
#define HCc  32
#define TRIc 499500
#define HIDc 128
#define EPSc 1e-5f
#define HPLANE (Bc * NPc * HCc)

// ---------------- persistent scratch ----------------
__device__ int    g_bar[32];
__device__ int    g_cursor;                  // gemm chunk cursor (memset per launch)
__device__ float  g_hbuf[2 * HPLANE];        // h planes (layers 0,1)
__device__ float  g_hv[64 * 20000];          // per-block v-tables: [blk][k][d] float4
__device__ float  g_emb[Bc * 96];
__device__ float  g_y1[Bc * HIDc];

// monotonic N-block barrier (replay-safe, never reset)
__device__ __forceinline__ void gbarN(int slot, int nb) {
    __syncthreads();
    if (threadIdx.x == 0) {
        __threadfence();
        int r = atomicAdd(&g_bar[slot], 1);
        int target = (r / nb + 1) * nb;
        while (atomicAdd(&g_bar[slot], 0) < target) { }
    }
    __syncthreads();
}

// fast tanh: exp-based, no overflow, rel err ~1e-6
__device__ __forceinline__ float ftanh(float x) {
    float ax = fabsf(x);
    float e = __expf(-2.f * ax);
    float r = __fdividef(1.f - e, 1.f + e);
    return copysignf(r, x);
}

// ---------------- cheb smem layout (floats) ----------------
#define SM_A    0          // 4000 (float4[1000])   | aliased: pDeg/pCnt/pCur
#define SM_B    4000       // 4000                  | aliased: pScan
#define SM_EM   8000       // 20000 (float2 per edge: {w, idx-bits})
#define SM_ROW  28000      // 1008
#define SM_W    29008      // 640 (5x32x4)
#define SM_POOL 29648      // 128 (32 warps x 4)
#define SM_TOT  29776      // 119104 bytes

// ---------------- float4 smem gather (packed edge meta) ----------------
__device__ __forceinline__ float4 gat4(const float4* __restrict__ S,
                                       const float2* __restrict__ sEm,
                                       const int* __restrict__ sRow, int d) {
    int i0 = sRow[d], i1 = sRow[d + 1];
    float4 a = make_float4(0.f, 0.f, 0.f, 0.f);
#pragma unroll 2
    for (int i = i0; i < i1; i++) {
        float2 m = sEm[i];
        float4 sv = S[__float_as_int(m.y)];
        a.x = fmaf(m.x, sv.x, a.x);
        a.y = fmaf(m.x, sv.y, a.y);
        a.z = fmaf(m.x, sv.z, a.z);
        a.w = fmaf(m.x, sv.w, a.w);
    }
    return a;
}

// ---------------- one ChebConv layer: node-per-thread, 4 channels ----------------
// mode 0: v_k[d] = cw0[k][d][ch0..ch0+4)   (layer-0 identity input)
// mode 1: v_k[d] = vt4[k*1000 + d]
__device__ void run_layer(int L, int mode, int b, int ch0, int t,
                          float4* sA4, float4* sB4,
                          const int* sRow, const float2* sEm,
                          const float* __restrict__ vsrc, const float4* __restrict__ vt4,
                          const float* __restrict__ cbL, float* sPool)
{
#define VR(k, d) (mode == 0 ? __ldg((const float4*)(vsrc + (k) * 32000 + (d) * 32 + ch0)) \
                            : __ldcg(vt4 + (k) * 1000 + (d)))
    int d = t;
    bool act = (d < NPc);
    if (act) sA4[d] = VR(4, d);
    __syncthreads();
    if (act) {
        float4 g = gat4(sA4, sEm, sRow, d);
        float4 v = VR(3, d);
        sB4[d] = make_float4(fmaf(2.f, g.x, v.x), fmaf(2.f, g.y, v.y),
                             fmaf(2.f, g.z, v.z), fmaf(2.f, g.w, v.w));
    }
    __syncthreads();
    if (act) {
        float4 g = gat4(sB4, sEm, sRow, d);
        float4 v = VR(2, d);
        float4 o = sA4[d];
        sA4[d] = make_float4(fmaf(2.f, g.x, v.x) - o.x, fmaf(2.f, g.y, v.y) - o.y,
                             fmaf(2.f, g.z, v.z) - o.z, fmaf(2.f, g.w, v.w) - o.w);
    }
    __syncthreads();
    if (act) {
        float4 g = gat4(sA4, sEm, sRow, d);
        float4 v = VR(1, d);
        float4 o = sB4[d];
        sB4[d] = make_float4(fmaf(2.f, g.x, v.x) - o.x, fmaf(2.f, g.y, v.y) - o.y,
                             fmaf(2.f, g.z, v.z) - o.z, fmaf(2.f, g.w, v.w) - o.w);
    }
    __syncthreads();
    // final: h = tanh(v0 + G(B) - A + bias)
    float4 pool = make_float4(0.f, 0.f, 0.f, 0.f);
    if (act) {
        float4 g = gat4(sB4, sEm, sRow, d);
        float4 v = VR(0, d);
        float4 o = sA4[d];
        float4 bias4 = __ldg((const float4*)(cbL + ch0));
        float4 h;
        h.x = ftanh(v.x + g.x - o.x + bias4.x);
        h.y = ftanh(v.y + g.y - o.y + bias4.y);
        h.z = ftanh(v.z + g.z - o.z + bias4.z);
        h.w = ftanh(v.w + g.w - o.w + bias4.w);
        pool = h;
        if (L < 2)
            *(float4*)(g_hbuf + L * HPLANE + b * NPc * HCc + d * HCc + ch0) = h;
    }
    // pool reduce: warp shuffles, per-warp smem, direct store (block owns its cols)
#pragma unroll
    for (int off = 16; off >= 1; off >>= 1) {
        pool.x += __shfl_down_sync(0xFFFFFFFFu, pool.x, off);
        pool.y += __shfl_down_sync(0xFFFFFFFFu, pool.y, off);
        pool.z += __shfl_down_sync(0xFFFFFFFFu, pool.z, off);
        pool.w += __shfl_down_sync(0xFFFFFFFFu, pool.w, off);
    }
    int wid = t >> 5, lid = t & 31;
    if (lid == 0) *(float4*)(sPool + wid * 4) = pool;
    __syncthreads();
    if (t < 4) {
        float s = 0.f;
#pragma unroll
        for (int w = 0; w < 32; w++) s += sPool[w * 4 + t];
        g_emb[b * 96 + L * 32 + ch0 + t] = s;
    }
    __syncthreads();
#undef VR
}

// ---------------- v-table pass: vt4[k*1000+d] = h[d][:] @ W[k][:, ch0..ch0+4) ----------------
__device__ void vpass(const float* __restrict__ hprev,   // batch base [d][32]
                      const float* __restrict__ cwL,     // (5,32,32)
                      float4* __restrict__ vt4, float* sW, int ch0, int t)
{
    for (int idx = t; idx < 640; idx += 1024) {
        int c = idx & 3, j = (idx >> 2) & 31, k = idx >> 7;
        sW[idx] = __ldg(cwL + k * 1024 + j * 32 + ch0 + c);
    }
    __syncthreads();
    int d = t;
    if (d < NPc) {
        float4 hv[8];
#pragma unroll
        for (int q = 0; q < 8; q++)
            hv[q] = __ldcg((const float4*)(hprev + d * 32 + q * 4));
        const float* hh = (const float*)hv;
#pragma unroll
        for (int k = 0; k < 5; k++) {
            float4 acc = make_float4(0.f, 0.f, 0.f, 0.f);
#pragma unroll
            for (int j = 0; j < 32; j++) {
                float hj = hh[j];
                float4 wr = *(const float4*)&sW[k * 128 + j * 4];
                acc.x = fmaf(hj, wr.x, acc.x);
                acc.y = fmaf(hj, wr.y, acc.y);
                acc.z = fmaf(hj, wr.z, acc.z);
                acc.w = fmaf(hj, wr.w, acc.w);
            }
            vt4[k * 1000 + d] = acc;
        }
    }
    __syncthreads();
}

// ---------------- the cheb kernel: 64 blocks x 1024 threads ----------------
__global__ void __launch_bounds__(1024, 1)
cheb_kernel(const int* __restrict__ src, const int* __restrict__ dst, int E,
            const float* __restrict__ cw0, const float* __restrict__ cb0,
            const float* __restrict__ cw1, const float* __restrict__ cb1,
            const float* __restrict__ cw2, const float* __restrict__ cb2)
{
    extern __shared__ float sm[];
    float4* sA4 = (float4*)(sm + SM_A);
    float4* sB4 = (float4*)(sm + SM_B);
    float2* sEm = (float2*)(sm + SM_EM);
    int* sRow   = (int*)(sm + SM_ROW);
    float* sW   = sm + SM_W;
    float* sPool= sm + SM_POOL;
    // CSR-build scratch aliased over sA/sB (dead until first pass)
    int* pDeg  = (int*)(sm + SM_A);
    int* pCnt  = (int*)(sm + SM_A) + 1000;
    int* pCur  = (int*)(sm + SM_A) + 2000;
    int* pScan = (int*)(sm + SM_B);

    const int t = threadIdx.x, blk = blockIdx.x;
    const int b = blk >> 3, r = blk & 7;
    const int ch0 = r * 4;
    const int EB = E / Bc;
    const int e0 = b * EB;
    float4* vt4 = (float4*)(g_hv + blk * 20000);

    // ---- in-block CSR build for batch b ----
    if (t < NPc) { pDeg[t] = 0; pCnt[t] = 0; }
    __syncthreads();
    for (int e = e0 + t; e < e0 + EB; e += 1024) {
        atomicAdd(&pDeg[__ldg(src + e) - b * NPc], 1);
        atomicAdd(&pCnt[__ldg(dst + e) - b * NPc], 1);
    }
    __syncthreads();
    {   // exclusive scan of pCnt
        int c = (t < NPc) ? pCnt[t] : 0;
        pScan[t] = c;
        __syncthreads();
        for (int off = 1; off < 1024; off <<= 1) {
            int v = (t >= off) ? pScan[t - off] : 0;
            __syncthreads();
            pScan[t] += v;
            __syncthreads();
        }
        if (t < NPc) { sRow[t] = pScan[t] - c; pCur[t] = pScan[t] - c; }
        if (t == 0) sRow[NPc] = pScan[1023];
    }
    __syncthreads();
    for (int e = e0 + t; e < e0 + EB; e += 1024) {
        int s_ = __ldg(src + e) - b * NPc;
        int d_ = __ldg(dst + e) - b * NPc;
        int ds = pDeg[s_], dd = pDeg[d_];
        float w = (ds > 0 && dd > 0) ? -rsqrtf((float)ds) * rsqrtf((float)dd) : 0.f;
        int pos = atomicAdd(&pCur[d_], 1);
        sEm[pos] = make_float2(w, __int_as_float(s_));
    }
    __syncthreads();   // scratch dead; sA/sB reusable

    // ---- layer 0 (v-tables = cw0 planes) ----
    run_layer(0, 0, b, ch0, t, sA4, sB4, sRow, sEm, cw0, nullptr, cb0, sPool);

    __threadfence();
    gbarN(b * 2 + 0, 8);
    vpass(g_hbuf + 0 * HPLANE + b * NPc * HCc, cw1, vt4, sW, ch0, t);
    run_layer(1, 1, b, ch0, t, sA4, sB4, sRow, sEm, nullptr, vt4, cb1, sPool);

    __threadfence();
    gbarN(b * 2 + 1, 8);
    vpass(g_hbuf + 1 * HPLANE + b * NPc * HCc, cw2, vt4, sW, ch0, t);
    run_layer(2, 1, b, ch0, t, sA4, sB4, sRow, sEm, nullptr, vt4, cb2, sPool);
}

// ---------------- GEMM kernel: dynamic chunks, 8-deep prefetch ----------------
#define GNB   296
#define GCH   256
#define GNCH  ((TRIc + GCH - 1) / GCH)   // 1952

__device__ __forceinline__ void triidx(int f, int& i, int& j) {
    float disc = 3996001.0f - 8.0f * (float)f;
    float sq = sqrtf(fmaxf(disc, 0.f));
    i = (int)((1999.0f - sq) * 0.5f);
    i = max(0, min(i, Fc - 2));
    while (i + 1 <= Fc - 2 && (((long long)(i + 1) * (1999 - (i + 1))) >> 1) <= (long long)f) i++;
    while (i > 0 && (((long long)i * (1999 - i)) >> 1) > (long long)f) i--;
    int Si = (int)(((long long)i * (1999 - i)) >> 1);
    j = i + 1 + (f - Si);
}

__global__ void __launch_bounds__(256, 2)
gemm_kernel(const float* __restrict__ x, const float* __restrict__ W1,
            const float* __restrict__ bng, const float* __restrict__ bnb)
{
    __shared__ float sfb[2][GCH * 8];
    __shared__ float sred[4096];
    __shared__ int sChunk;
    int t = threadIdx.x, wp = t >> 5, l = t & 31;
    float acc[Bc][4];
#pragma unroll
    for (int b = 0; b < Bc; b++)
#pragma unroll
        for (int q = 0; q < 4; q++) acc[b][q] = 0.f;

    if (t == 0) sChunk = atomicAdd(&g_cursor, 1);
    __syncthreads();
    int c = sChunk;
    __syncthreads();
    if (c < GNCH) {
        int f = c * GCH + t;
        float res[Bc];
        if (f < TRIc) {
            int i, j; triidx(f, i, j);
            float v[Bc]; float m = 0.f;
#pragma unroll
            for (int b = 0; b < Bc; b++) { v[b] = __ldg(x + ((size_t)(b * Fc + i) * Fc + j)); m += v[b]; }
            m *= 0.125f;
            float var = 0.f;
#pragma unroll
            for (int b = 0; b < Bc; b++) { float dd = v[b] - m; var = fmaf(dd, dd, var); }
            var *= 0.125f;
            float sc = rsqrtf(var + EPSc) * __ldg(bng + f);
            float sh = __ldg(bnb + f);
#pragma unroll
            for (int b = 0; b < Bc; b++) res[b] = (v[b] - m) * sc + sh;
        } else {
#pragma unroll
            for (int b = 0; b < Bc; b++) res[b] = 0.f;
        }
        *(float4*)&sfb[0][t * 8]     = make_float4(res[0], res[1], res[2], res[3]);
        *(float4*)&sfb[0][t * 8 + 4] = make_float4(res[4], res[5], res[6], res[7]);
    }
    __syncthreads();

    int p = 0;
    while (c < GNCH) {
        if (t == 0) sChunk = atomicAdd(&g_cursor, 1);
        __syncthreads();
        int cn = sChunk;
        __syncthreads();
        bool hasN = (cn < GNCH);
        float xv[Bc]; float bgv = 0.f, bbv = 0.f; bool val = false;
        if (hasN) {
            int fN = cn * GCH + t;
            val = (fN < TRIc);
            if (val) {
                int i, j; triidx(fN, i, j);
#pragma unroll
                for (int b = 0; b < Bc; b++)
                    xv[b] = __ldg(x + ((size_t)(b * Fc + i) * Fc + j));
                bgv = __ldg(bng + fN);
                bbv = __ldg(bnb + fN);
            }
        }
        {
            int fbase = c * GCH;
            int r0 = wp * 32;
            const float* buf = sfb[p];
            for (int rb = 0; rb < 32; rb += 8) {
                float4 w[8];
#pragma unroll
                for (int u = 0; u < 8; u++) {
                    int f2 = min(fbase + r0 + rb + u, TRIc - 1);
                    w[u] = __ldcs((const float4*)(W1 + (size_t)f2 * HIDc + l * 4));
                }
#pragma unroll
                for (int u = 0; u < 8; u++) {
                    int fl = r0 + rb + u;
                    float4 f0 = *(const float4*)&buf[fl * 8];
                    float4 f1 = *(const float4*)&buf[fl * 8 + 4];
                    acc[0][0] = fmaf(f0.x, w[u].x, acc[0][0]); acc[0][1] = fmaf(f0.x, w[u].y, acc[0][1]);
                    acc[0][2] = fmaf(f0.x, w[u].z, acc[0][2]); acc[0][3] = fmaf(f0.x, w[u].w, acc[0][3]);
                    acc[1][0] = fmaf(f0.y, w[u].x, acc[1][0]); acc[1][1] = fmaf(f0.y, w[u].y, acc[1][1]);
                    acc[1][2] = fmaf(f0.y, w[u].z, acc[1][2]); acc[1][3] = fmaf(f0.y, w[u].w, acc[1][3]);
                    acc[2][0] = fmaf(f0.z, w[u].x, acc[2][0]); acc[2][1] = fmaf(f0.z, w[u].y, acc[2][1]);
                    acc[2][2] = fmaf(f0.z, w[u].z, acc[2][2]); acc[2][3] = fmaf(f0.z, w[u].w, acc[2][3]);
                    acc[3][0] = fmaf(f0.w, w[u].x, acc[3][0]); acc[3][1] = fmaf(f0.w, w[u].y, acc[3][1]);
                    acc[3][2] = fmaf(f0.w, w[u].z, acc[3][2]); acc[3][3] = fmaf(f0.w, w[u].w, acc[3][3]);
                    acc[4][0] = fmaf(f1.x, w[u].x, acc[4][0]); acc[4][1] = fmaf(f1.x, w[u].y, acc[4][1]);
                    acc[4][2] = fmaf(f1.x, w[u].z, acc[4][2]); acc[4][3] = fmaf(f1.x, w[u].w, acc[4][3]);
                    acc[5][0] = fmaf(f1.y, w[u].x, acc[5][0]); acc[5][1] = fmaf(f1.y, w[u].y, acc[5][1]);
                    acc[5][2] = fmaf(f1.y, w[u].z, acc[5][2]); acc[5][3] = fmaf(f1.y, w[u].w, acc[5][3]);
                    acc[6][0] = fmaf(f1.z, w[u].x, acc[6][0]); acc[6][1] = fmaf(f1.z, w[u].y, acc[6][1]);
                    acc[6][2] = fmaf(f1.z, w[u].z, acc[6][2]); acc[6][3] = fmaf(f1.z, w[u].w, acc[6][3]);
                    acc[7][0] = fmaf(f1.w, w[u].x, acc[7][0]); acc[7][1] = fmaf(f1.w, w[u].y, acc[7][1]);
                    acc[7][2] = fmaf(f1.w, w[u].z, acc[7][2]); acc[7][3] = fmaf(f1.w, w[u].w, acc[7][3]);
                }
            }
        }
        if (hasN) {
            float res[Bc];
            if (val) {
                float m = 0.f;
#pragma unroll
                for (int b = 0; b < Bc; b++) m += xv[b];
                m *= 0.125f;
                float var = 0.f;
#pragma unroll
                for (int b = 0; b < Bc; b++) { float dd = xv[b] - m; var = fmaf(dd, dd, var); }
                var *= 0.125f;
                float sc = rsqrtf(var + EPSc) * bgv;
#pragma unroll
                for (int b = 0; b < Bc; b++) res[b] = (xv[b] - m) * sc + bbv;
            } else {
#pragma unroll
                for (int b = 0; b < Bc; b++) res[b] = 0.f;
            }
            *(float4*)&sfb[p ^ 1][t * 8]     = make_float4(res[0], res[1], res[2], res[3]);
            *(float4*)&sfb[p ^ 1][t * 8 + 4] = make_float4(res[4], res[5], res[6], res[7]);
        }
        __syncthreads();
        c = cn;
        p ^= 1;
    }

    for (int half = 4; half >= 1; half >>= 1) {
        if (wp >= half && wp < 2 * half) {
            float* reg = sred + (wp - half) * 1024;
#pragma unroll
            for (int b = 0; b < Bc; b++)
                *(float4*)&reg[b * HIDc + l * 4] =
                    make_float4(acc[b][0], acc[b][1], acc[b][2], acc[b][3]);
        }
        __syncthreads();
        if (wp < half) {
            float* reg = sred + wp * 1024;
#pragma unroll
            for (int b = 0; b < Bc; b++) {
                float4 z = *(const float4*)&reg[b * HIDc + l * 4];
                acc[b][0] += z.x; acc[b][1] += z.y; acc[b][2] += z.z; acc[b][3] += z.w;
            }
        }
        __syncthreads();
    }
    if (wp == 0) {
#pragma unroll
        for (int b = 0; b < Bc; b++)
#pragma unroll
            for (int q = 0; q < 4; q++)
                atomicAdd(&g_y1[b * HIDc + l * 4 + q], acc[b][q]);
    }
}

// ---------------- head ----------------
__global__ void head_kernel(const float* __restrict__ bnhg, const float* __restrict__ bnhb,
                            const float* __restrict__ b1,
                            const float* __restrict__ g1, const float* __restrict__ be1,
                            const float* __restrict__ W2, const float* __restrict__ b2,
                            const float* __restrict__ g2, const float* __restrict__ be2,
                            const float* __restrict__ W3, const float* __restrict__ b3,
                            const float* __restrict__ g3, const float* __restrict__ be3,
                            const float* __restrict__ W4, const float* __restrict__ b4,
                            float* __restrict__ out) {
    __shared__ float a1[8 * 128];
    __shared__ float a2[8 * 64];
    __shared__ float a3[8 * 64];
    __shared__ float lg[16];
    int t = threadIdx.x;

    if (t < 96) {
        float e[Bc]; float m = 0.f;
#pragma unroll
        for (int b = 0; b < Bc; b++) { e[b] = __ldcg(&g_emb[b * 96 + t]) * (1.f / (float)NPc); m += e[b]; }
        m *= 0.125f;
        float v = 0.f;
#pragma unroll
        for (int b = 0; b < Bc; b++) { float dd = e[b] - m; v = fmaf(dd, dd, v); }
        v *= 0.125f;
        float sc = rsqrtf(v + EPSc) * __ldg(bnhg + t);
        float sh = __ldg(bnhb + t);
#pragma unroll
        for (int b = 0; b < Bc; b++) out[16 + b * 96 + t] = (e[b] - m) * sc + sh;
    }

    for (int idx = t; idx < 1024; idx += 256) a1[idx] = __ldcg(&g_y1[idx]) + __ldg(&b1[idx & 127]);
    __syncthreads();
    if (t < 128) {
        float m = 0.f;
#pragma unroll
        for (int b = 0; b < Bc; b++) m += a1[b * 128 + t];
        m *= 0.125f;
        float v = 0.f;
#pragma unroll
        for (int b = 0; b < Bc; b++) { float dd = a1[b * 128 + t] - m; v = fmaf(dd, dd, v); }
        v *= 0.125f;
        float sc = rsqrtf(v + EPSc) * __ldg(g1 + t);
        float sh = __ldg(be1 + t);
#pragma unroll
        for (int b = 0; b < Bc; b++) {
            float z = (a1[b * 128 + t] - m) * sc + sh;
            a1[b * 128 + t] = z > 0.f ? z : 0.f;
        }
    }
    __syncthreads();
    for (int idx = t; idx < 512; idx += 256) {
        int b = idx >> 6, h = idx & 63;
        float s = __ldg(b2 + h);
        for (int j = 0; j < 128; j++) s = fmaf(a1[b * 128 + j], __ldg(W2 + j * 64 + h), s);
        a2[idx] = s;
    }
    __syncthreads();
    if (t < 64) {
        float m = 0.f;
#pragma unroll
        for (int b = 0; b < Bc; b++) m += a2[b * 64 + t];
        m *= 0.125f;
        float v = 0.f;
#pragma unroll
        for (int b = 0; b < Bc; b++) { float dd = a2[b * 64 + t] - m; v = fmaf(dd, dd, v); }
        v *= 0.125f;
        float sc = rsqrtf(v + EPSc) * __ldg(g2 + t);
        float sh = __ldg(be2 + t);
#pragma unroll
        for (int b = 0; b < Bc; b++) {
            float z = (a2[b * 64 + t] - m) * sc + sh;
            a2[b * 64 + t] = z > 0.f ? z : 0.f;
        }
    }
    __syncthreads();
    for (int idx = t; idx < 512; idx += 256) {
        int b = idx >> 6, h = idx & 63;
        float s = __ldg(b3 + h);
        for (int j = 0; j < 64; j++) s = fmaf(a2[b * 64 + j], __ldg(W3 + j * 64 + h), s);
        a3[idx] = s;
    }
    __syncthreads();
    if (t < 64) {
        float m = 0.f;
#pragma unroll
        for (int b = 0; b < Bc; b++) m += a3[b * 64 + t];
        m *= 0.125f;
        float v = 0.f;
#pragma unroll
        for (int b = 0; b < Bc; b++) { float dd = a3[b * 64 + t] - m; v = fmaf(dd, dd, v); }
        v *= 0.125f;
        float sc = rsqrtf(v + EPSc) * __ldg(g3 + t);
        float sh = __ldg(be3 + t);
#pragma unroll
        for (int b = 0; b < Bc; b++) {
            float z = (a3[b * 64 + t] - m) * sc + sh;
            a3[b * 64 + t] = z > 0.f ? z : 0.f;
        }
    }
    __syncthreads();
    if (t < 16) {
        int b = t >> 1, c = t & 1;
        float s = __ldg(b4 + c);
        for (int j = 0; j < 64; j++) s = fmaf(a3[b * 64 + j], __ldg(W4 + j * 2 + c), s);
        lg[t] = s;
    }
    __syncthreads();
    if (t < 8) {
        float l0 = lg[t * 2], l1 = lg[t * 2 + 1];
        float m = fmaxf(l0, l1);
        float lse = m + logf(expf(l0 - m) + expf(l1 - m));
        out[t * 2 + 0] = l0 - lse;
        out[t * 2 + 1] = l1 - lse;
    }
}

// ---------------- host driver ----------------
extern "C" void kernel_launch(void* const* d_in, const int* in_sizes, int n_in,
                              void* d_out, int out_size) {
    const float* x    = (const float*)d_in[0];
    const int*   ei   = (const int*)d_in[1];
    int E = in_sizes[1] / 2;
    const int* src = ei;
    const int* dst = ei + E;
    const float* cw0  = (const float*)d_in[3];
    const float* cb0  = (const float*)d_in[4];
    const float* cw1  = (const float*)d_in[5];
    const float* cb1  = (const float*)d_in[6];
    const float* cw2  = (const float*)d_in[7];
    const float* cb2  = (const float*)d_in[8];
    const float* bnhg = (const float*)d_in[9];
    const float* bnhb = (const float*)d_in[10];
    const float* bng  = (const float*)d_in[11];
    const float* bnb  = (const float*)d_in[12];
    const float* w1   = (const float*)d_in[13];
    const float* b1   = (const float*)d_in[14];
    const float* g1   = (const float*)d_in[15];
    const float* be1  = (const float*)d_in[16];
    const float* W2   = (const float*)d_in[17];
    const float* b2   = (const float*)d_in[18];
    const float* g2   = (const float*)d_in[19];
    const float* be2  = (const float*)d_in[20];
    const float* W3   = (const float*)d_in[21];
    const float* b3   = (const float*)d_in[22];
    const float* g3   = (const float*)d_in[23];
    const float* be3  = (const float*)d_in[24];
    const float* W4   = (const float*)d_in[25];
    const float* b4   = (const float*)d_in[26];
    float* out = (float*)d_out;

    void* y1ptr = nullptr;
    void* curptr = nullptr;
    cudaGetSymbolAddress(&y1ptr, g_y1);
    cudaGetSymbolAddress(&curptr, g_cursor);

    cudaStream_t s2 = 0;
    cudaEvent_t evF = 0, evJ = 0;
    bool forked = (cudaStreamCreateWithFlags(&s2, cudaStreamNonBlocking) == cudaSuccess) &&
                  (cudaEventCreateWithFlags(&evF, cudaEventDisableTiming) == cudaSuccess) &&
                  (cudaEventCreateWithFlags(&evJ, cudaEventDisableTiming) == cudaSuccess);
    if (!forked) s2 = 0;

    if (forked) {
        cudaEventRecord(evF, 0);
        cudaStreamWaitEvent(s2, evF, 0);
    }

    // cheb first (64 big-smem blocks grab their SMs immediately)
    cudaFuncSetAttribute(cheb_kernel, cudaFuncAttributeMaxDynamicSharedMemorySize,
                         SM_TOT * (int)sizeof(float));
    cheb_kernel<<<64, 1024, SM_TOT * sizeof(float)>>>(src, dst, E,
                                                      cw0, cb0, cw1, cb1, cw2, cb2);

    cudaMemsetAsync(y1ptr, 0, Bc * HIDc * sizeof(float), s2);
    cudaMemsetAsync(curptr, 0, sizeof(int), s2);
    gemm_kernel<<<GNB, 256, 0, s2>>>(x, w1, bng, bnb);
    if (forked) cudaEventRecord(evJ, s2);

    if (forked) cudaStreamWaitEvent(0, evJ, 0);
    head_kernel<<<1, 256>>>(bnhg, bnhb, b1, g1, be1, W2, b2, g2, be2,
                            W3, b3, g3, be3, W4, b4, out);
}